// round 1
// baseline (speedup 1.0000x reference)
#include <cuda_runtime.h>

// LSTMModel: 2-layer LSTM (B=256, T=512, I=64, H=256) + FC(H->1).
// Single persistent kernel, fp32 FFMA, software grid barrier per timestep.
// Input projection folded into the per-step GEMM (K = H + Kin).
// Cell state c lives in CTA shared memory for the whole layer.
// h double-buffered in device global; __ldcg/__stcg for cross-SM coherence.

#define BB   256   // batch
#define TT   512   // time
#define II   64    // input dim (layer 0)
#define HH   256   // hidden dim

#define GRID 128   // <= 148 SMs -> all CTAs co-resident -> spin barrier is safe
#define NTHR 128
#define KC   32    // K-chunk

// ---------------- device globals (scratch; no cudaMalloc allowed) ----------
__device__ float g_hbuf[2][BB * HH];                   // double-buffered h
__device__ float g_h1[(size_t)BB * TT * HH];           // layer-0 output archive
__device__ unsigned long long g_gen;                   // barrier generation
__device__ unsigned int       g_count;                 // barrier arrivals

// ---------------- grid barrier (sense-reversal, release/acquire) -----------
__device__ __forceinline__ void grid_barrier() {
    __syncthreads();
    __threadfence();                 // release: make my CTA's stores visible
    if (threadIdx.x == 0) {
        unsigned long long my = *(volatile unsigned long long*)&g_gen;
        unsigned prev = atomicAdd(&g_count, 1u);
        if (prev == GRID - 1u) {
            g_count = 0u;
            __threadfence();
            atomicAdd(&g_gen, 1ULL);
        } else {
            while (*(volatile unsigned long long*)&g_gen == my) __nanosleep(64);
        }
        __threadfence();             // acquire
    }
    __syncthreads();
}

// ---------------- activations (fast, accurate enough: err ~1e-6) -----------
__device__ __forceinline__ float fsigmoid(float x) {
    return 1.0f / (1.0f + __expf(-x));
}
__device__ __forceinline__ float ftanh(float x) {
    x = fminf(15.0f, fmaxf(-15.0f, x));
    float t = __expf(2.0f * x);
    return (t - 1.0f) / (t + 1.0f);
}

// ---------------- shared memory layout -------------------------------------
struct Smem {
    float As[2][KC][36];   // h/x tile, k-major, padded (36*4=144B, 16B aligned)
    float Ws[2][KC][68];   // weight tile, k-major, padded (68*4=272B aligned)
    float Sg[32][68];      // per-step gate pre-activations [b][cc]
    float cs[32][16];      // cell state tile [b][u], persistent per layer
    float bias_s[64];      // bih+bhh for this CTA's 64 columns
};  // ~37.6 KB static

// A tile: 32 b-rows x KC k.  Each thread loads 2 float4 (k-contiguous).
template<int KIN>
__device__ __forceinline__ void load_A(float4 (&ar)[2], int cidx, int t, int mbase,
                                       const float* __restrict__ hr,
                                       const float* __restrict__ xin) {
    const bool hpart = (cidx * KC < HH);
#pragma unroll
    for (int i = 0; i < 2; i++) {
        int idx = threadIdx.x + i * NTHR;
        int bb  = idx >> 3;
        int k   = cidx * KC + (idx & 7) * 4;
        const float* src;
        if (hpart) src = hr + (mbase + bb) * HH + k;
        else       src = xin + (mbase + bb) * TT * KIN + t * KIN + (k - HH);
        ar[i] = __ldcg((const float4*)src);
    }
}

__device__ __forceinline__ void store_A(Smem& sm, int buf, const float4 (&ar)[2]) {
#pragma unroll
    for (int i = 0; i < 2; i++) {
        int idx = threadIdx.x + i * NTHR;
        int bb  = idx >> 3;
        int k4  = (idx & 7) * 4;
        sm.As[buf][k4 + 0][bb] = ar[i].x;
        sm.As[buf][k4 + 1][bb] = ar[i].y;
        sm.As[buf][k4 + 2][bb] = ar[i].z;
        sm.As[buf][k4 + 3][bb] = ar[i].w;
    }
}

// W tile: 64 cols x KC k. col cc -> gate = cc>>4, u = cc&15, row = gate*H+jbase+u
template<int KIN>
__device__ __forceinline__ void load_W(float4 (&wr)[4], int cidx, int jbase,
                                       const float* __restrict__ Wih,
                                       const float* __restrict__ Whh) {
    const bool hpart = (cidx * KC < HH);
#pragma unroll
    for (int i = 0; i < 4; i++) {
        int idx  = threadIdx.x + i * NTHR;
        int cc   = idx >> 3;
        int k4   = (idx & 7) * 4;
        int gate = cc >> 4, u = cc & 15;
        int grow = gate * HH + jbase + u;
        const float* src;
        if (hpart) src = Whh + grow * HH + cidx * KC + k4;
        else       src = Wih + grow * KIN + cidx * KC + k4 - HH;
        wr[i] = *(const float4*)src;   // cached: weight slice becomes L1-resident
    }
}

__device__ __forceinline__ void store_W(Smem& sm, int buf, const float4 (&wr)[4]) {
#pragma unroll
    for (int i = 0; i < 4; i++) {
        int idx = threadIdx.x + i * NTHR;
        int cc  = idx >> 3;
        int k4  = (idx & 7) * 4;
        sm.Ws[buf][k4 + 0][cc] = wr[i].x;
        sm.Ws[buf][k4 + 1][cc] = wr[i].y;
        sm.Ws[buf][k4 + 2][cc] = wr[i].z;
        sm.Ws[buf][k4 + 3][cc] = wr[i].w;
    }
}

// ---------------- one LSTM layer -------------------------------------------
template<int KIN, bool ARCHIVE>
__device__ void run_layer(Smem& sm, const float* __restrict__ xin,
                          const float* __restrict__ Wih,
                          const float* __restrict__ Whh,
                          const float* __restrict__ bih,
                          const float* __restrict__ bhh) {
    const int tid   = threadIdx.x;
    const int mbase = (blockIdx.x >> 4) * 32;   // 8 m-tiles of 32 batch rows
    const int jbase = (blockIdx.x & 15) * 16;   // 16 j-tiles of 16 hidden cols
    constexpr int NCH = (HH + KIN) / KC;

    // layer init: zero c tile, zero h read-buffer (buf 0), cache biases
    for (int idx = tid; idx < 32 * 16; idx += NTHR) {
        int bb = idx >> 4, u = idx & 15;
        sm.cs[bb][u] = 0.0f;
        __stcg(&g_hbuf[0][(mbase + bb) * HH + jbase + u], 0.0f);
    }
    if (tid < 64) {
        int gate = tid >> 4, u = tid & 15;
        int grow = gate * HH + jbase + u;
        sm.bias_s[tid] = bih[grow] + bhh[grow];
    }
    grid_barrier();

    for (int t = 0; t < TT; t++) {
        const float* hr = g_hbuf[t & 1];
        float*       hw = g_hbuf[(t & 1) ^ 1];

        float acc[4][4];
#pragma unroll
        for (int a = 0; a < 4; a++)
#pragma unroll
            for (int b = 0; b < 4; b++) acc[a][b] = 0.0f;

        float4 ar[2], wr[4];
        // prologue: chunk 0 -> smem buf 0
        load_A<KIN>(ar, 0, t, mbase, hr, xin);
        load_W<KIN>(wr, 0, jbase, Wih, Whh);
        store_A(sm, 0, ar);
        store_W(sm, 0, wr);
        __syncthreads();

        const int tb4 = (tid & 7) * 4;
        const int tc4 = (tid >> 3) * 4;

        for (int c = 0; c < NCH; c++) {
            const bool more = (c + 1 < NCH);
            if (more) {
                load_A<KIN>(ar, c + 1, t, mbase, hr, xin);
                load_W<KIN>(wr, c + 1, jbase, Wih, Whh);
            }
            const int buf = c & 1;
#pragma unroll 8
            for (int kk = 0; kk < KC; kk++) {
                float4 a = *(const float4*)&sm.As[buf][kk][tb4];
                float4 w = *(const float4*)&sm.Ws[buf][kk][tc4];
                acc[0][0] += a.x * w.x; acc[0][1] += a.x * w.y;
                acc[0][2] += a.x * w.z; acc[0][3] += a.x * w.w;
                acc[1][0] += a.y * w.x; acc[1][1] += a.y * w.y;
                acc[1][2] += a.y * w.z; acc[1][3] += a.y * w.w;
                acc[2][0] += a.z * w.x; acc[2][1] += a.z * w.y;
                acc[2][2] += a.z * w.z; acc[2][3] += a.z * w.w;
                acc[3][0] += a.w * w.x; acc[3][1] += a.w * w.y;
                acc[3][2] += a.w * w.z; acc[3][3] += a.w * w.w;
            }
            if (more) {
                store_A(sm, buf ^ 1, ar);
                store_W(sm, buf ^ 1, wr);
            }
            __syncthreads();
        }

        // stage gate pre-activations to smem, then per-(b,u) LSTM update
        const int tb = tid & 7, tc = tid >> 3;
#pragma unroll
        for (int bi = 0; bi < 4; bi++) {
            float4 v = make_float4(acc[bi][0], acc[bi][1], acc[bi][2], acc[bi][3]);
            *(float4*)&sm.Sg[tb * 4 + bi][tc * 4] = v;
        }
        __syncthreads();

#pragma unroll
        for (int r = 0; r < 4; r++) {
            int pair = tid * 4 + r;          // 512 (b,u) pairs / 128 threads
            int bb = pair >> 4;
            int u  = pair & 15;
            float pi = sm.Sg[bb][u]      + sm.bias_s[u];
            float pf = sm.Sg[bb][16 + u] + sm.bias_s[16 + u];
            float pg = sm.Sg[bb][32 + u] + sm.bias_s[32 + u];
            float po = sm.Sg[bb][48 + u] + sm.bias_s[48 + u];
            float ig = fsigmoid(pi);
            float fg = fsigmoid(pf);
            float gg = ftanh(pg);
            float og = fsigmoid(po);
            float cv = fg * sm.cs[bb][u] + ig * gg;
            sm.cs[bb][u] = cv;
            float hv = og * ftanh(cv);
            __stcg(&hw[(mbase + bb) * HH + jbase + u], hv);
            if (ARCHIVE)
                __stcg(&g_h1[(size_t)((mbase + bb) * TT + t) * HH + jbase + u], hv);
        }
        grid_barrier();   // h(t) visible everywhere before step t+1 reads it
    }
}

// ---------------- full model -----------------------------------------------
__global__ void __launch_bounds__(NTHR, 1)
lstm_persistent_kernel(const float* __restrict__ x,
                       const float* __restrict__ Wih0, const float* __restrict__ Whh0,
                       const float* __restrict__ bih0, const float* __restrict__ bhh0,
                       const float* __restrict__ Wih1, const float* __restrict__ Whh1,
                       const float* __restrict__ bih1, const float* __restrict__ bhh1,
                       const float* __restrict__ Wfc,  const float* __restrict__ bfc,
                       float* __restrict__ out) {
    __shared__ Smem sm;

    run_layer<II, true >(sm, x,    Wih0, Whh0, bih0, bhh0);
    run_layer<HH, false>(sm, g_h1, Wih1, Whh1, bih1, bhh1);
    // after 512 steps, final h2 sits in g_hbuf[0]; last barrier already passed

    if (blockIdx.x == 0) {
        for (int bb = threadIdx.x; bb < BB; bb += NTHR) {
            float s = bfc[0];
#pragma unroll 8
            for (int j = 0; j < HH; j++)
                s += __ldcg(&g_hbuf[0][bb * HH + j]) * Wfc[j];
            out[bb] = s;
        }
    }
}

// ---------------- harness entry --------------------------------------------
extern "C" void kernel_launch(void* const* d_in, const int* in_sizes, int n_in,
                              void* d_out, int out_size) {
    (void)in_sizes; (void)n_in; (void)out_size;
    const float* x    = (const float*)d_in[0];
    const float* Wih0 = (const float*)d_in[1];
    const float* Whh0 = (const float*)d_in[2];
    const float* bih0 = (const float*)d_in[3];
    const float* bhh0 = (const float*)d_in[4];
    const float* Wih1 = (const float*)d_in[5];
    const float* Whh1 = (const float*)d_in[6];
    const float* bih1 = (const float*)d_in[7];
    const float* bhh1 = (const float*)d_in[8];
    const float* Wfc  = (const float*)d_in[9];
    const float* bfc  = (const float*)d_in[10];

    lstm_persistent_kernel<<<GRID, NTHR>>>(x, Wih0, Whh0, bih0, bhh0,
                                           Wih1, Whh1, bih1, bhh1,
                                           Wfc, bfc, (float*)d_out);
}